// round 1
// baseline (speedup 1.0000x reference)
#include <cuda_runtime.h>
#include <cstddef>

// Problem constants (fixed shapes from reference)
#define BSZ  8
#define LEN  4096
#define HD   512
#define PD   256
#define MM   (BSZ * LEN)   // 32768 rows
#define KK   512           // GEMM K (both GEMMs)
#define NN   512           // GEMM N (2*PD real for GEMM1, HD for GEMM2)
#define NCH  16            // scan chunks
#define CLEN 256           // chunk length (NCH*CLEN == LEN)

// ---------------- scratch (device globals; no runtime allocation) -----------
__device__ __align__(16) float  d_W1[KK * NN];            // [k=h][n=2p+j]  (B_bar, re/im interleaved in n)
__device__ __align__(16) float  d_W2[KK * NN];            // [q=2p+j][h]    (2*Cre / -2*Cim)
__device__ __align__(16) float  d_Bu[(size_t)MM * NN];    // 64 MB: Bu as [m][2p+j] == float2 [m][p]
__device__ __align__(16) float  d_xs[(size_t)MM * NN];    // 64 MB: xs, same layout
__device__ float2 d_Lb[PD];
__device__ float2 d_gamma[PD];
__device__ float2 d_A256[PD];
__device__ float2 d_fin[BSZ * NCH * PD];
__device__ float2 d_carry[BSZ * NCH * PD];

// ---------------- prep: discretization ---------------------------------------
__global__ void k_prep1(const float* __restrict__ Lre, const float* __restrict__ Lim,
                        const float* __restrict__ lstep) {
    int p = threadIdx.x;
    if (p < PD) {
        float step = expf(lstep[p]);
        float re = Lre[p], im = Lim[p];
        float er = expf(re * step);
        float sphi, cphi;
        sincosf(im * step, &sphi, &cphi);
        float2 Lb = make_float2(er * cphi, er * sphi);
        // gamma = (Lb - 1) / Lambda  (complex division)
        float nr = Lb.x - 1.0f, ni = Lb.y;
        float den = re * re + im * im;
        float2 g = make_float2((nr * re + ni * im) / den, (ni * re - nr * im) / den);
        d_Lb[p] = Lb;
        d_gamma[p] = g;
        // Lambda_bar^CLEN via 8 complex squarings (CLEN = 256 = 2^8)
        float2 a = Lb;
        #pragma unroll
        for (int i = 0; i < 8; i++) {
            float ar = a.x * a.x - a.y * a.y;
            float ai = 2.0f * a.x * a.y;
            a = make_float2(ar, ai);
        }
        d_A256[p] = a;
    }
}

__global__ void k_prep2(const float* __restrict__ Bin, const float* __restrict__ Cin) {
    int idx = blockIdx.x * blockDim.x + threadIdx.x;
    if (idx < PD * HD) {
        int p = idx / HD, h = idx % HD;
        float2 g = d_gamma[p];
        float br = Bin[(p * HD + h) * 2 + 0];
        float bi = Bin[(p * HD + h) * 2 + 1];
        // B_bar = gamma * B_tilde
        d_W1[h * NN + 2 * p + 0] = g.x * br - g.y * bi;
        d_W1[h * NN + 2 * p + 1] = g.x * bi + g.y * br;
        float cr = Cin[(h * PD + p) * 2 + 0];
        float ci = Cin[(h * PD + p) * 2 + 1];
        // y = 2*Re(xs . C) = sum_q XS[q]*W2[q][h], q=2p -> 2*Cre, q=2p+1 -> -2*Cim
        d_W2[(2 * p + 0) * NN + h] =  2.0f * cr;
        d_W2[(2 * p + 1) * NN + h] = -2.0f * ci;
    }
}

// ---------------- fp32 SGEMM: 128x128 block, 16 K-slice, 256 thr, 8x8/thr ----
template <bool EPI>
__global__ void __launch_bounds__(256)
sgemm128(const float* __restrict__ A, const float* __restrict__ Bm,
         float* __restrict__ Cout,
         const float* __restrict__ Xskip, const float* __restrict__ Dv) {
    __shared__ float As[16][132];   // transposed A tile (+4 pad to soften store conflicts)
    __shared__ float Bs[16][128];

    const int tid = threadIdx.x;
    const int tx = tid & 15, ty = tid >> 4;
    const int m0 = blockIdx.y * 128;
    const int n0 = blockIdx.x * 128;

    float acc[8][8];
    #pragma unroll
    for (int i = 0; i < 8; i++)
        #pragma unroll
        for (int j = 0; j < 8; j++) acc[i][j] = 0.0f;

    const int a_row = tid >> 2;          // 0..63
    const int a_col = (tid & 3) << 2;    // 0,4,8,12
    const int b_row = tid >> 5;          // 0..7
    const int b_col = (tid & 31) << 2;   // 0..124

    for (int k0 = 0; k0 < KK; k0 += 16) {
        #pragma unroll
        for (int r = 0; r < 2; r++) {
            int row = a_row + r * 64;
            float4 v = *(const float4*)(A + (size_t)(m0 + row) * KK + k0 + a_col);
            As[a_col + 0][row] = v.x;
            As[a_col + 1][row] = v.y;
            As[a_col + 2][row] = v.z;
            As[a_col + 3][row] = v.w;
        }
        #pragma unroll
        for (int r = 0; r < 2; r++) {
            int row = b_row + r * 8;
            *(float4*)&Bs[row][b_col] =
                *(const float4*)(Bm + (size_t)(k0 + row) * NN + n0 + b_col);
        }
        __syncthreads();

        #pragma unroll
        for (int k = 0; k < 16; k++) {
            float av[8], bv[8];
            *(float4*)&av[0] = *(const float4*)&As[k][ty * 4];
            *(float4*)&av[4] = *(const float4*)&As[k][ty * 4 + 64];
            *(float4*)&bv[0] = *(const float4*)&Bs[k][tx * 4];
            *(float4*)&bv[4] = *(const float4*)&Bs[k][tx * 4 + 64];
            #pragma unroll
            for (int i = 0; i < 8; i++)
                #pragma unroll
                for (int j = 0; j < 8; j++)
                    acc[i][j] = fmaf(av[i], bv[j], acc[i][j]);
        }
        __syncthreads();
    }

    #pragma unroll
    for (int i = 0; i < 8; i++) {
        int m = m0 + ty * 4 + ((i < 4) ? i : (64 + i - 4));
        #pragma unroll
        for (int jj = 0; jj < 2; jj++) {
            int n = n0 + tx * 4 + jj * 64;
            float4 v = make_float4(acc[i][jj * 4 + 0], acc[i][jj * 4 + 1],
                                   acc[i][jj * 4 + 2], acc[i][jj * 4 + 3]);
            if (EPI) {
                float4 xv = *(const float4*)(Xskip + (size_t)m * NN + n);
                float4 dv = *(const float4*)(Dv + n);
                v.x = fmaf(dv.x, xv.x, v.x);
                v.y = fmaf(dv.y, xv.y, v.y);
                v.z = fmaf(dv.z, xv.z, v.z);
                v.w = fmaf(dv.w, xv.w, v.w);
            }
            *(float4*)(Cout + (size_t)m * NN + n) = v;
        }
    }
}

// ---------------- chunked complex scan ---------------------------------------
// Pass 1: per (b,chunk,p) local scan from zero init; store chunk finals.
__global__ void __launch_bounds__(256) k_scan1() {
    int t = blockIdx.x * 256 + threadIdx.x;     // (b*NCH+ch)*PD + p
    int p = t & (PD - 1);
    float2 a = d_Lb[p];
    const float2* bu = (const float2*)d_Bu + (size_t)(t >> 8) * (CLEN * PD) + p;
    float2 s = make_float2(0.0f, 0.0f);
    #pragma unroll 4
    for (int l = 0; l < CLEN; l++) {
        float2 v = bu[(size_t)l * PD];
        float sr = fmaf(a.x, s.x, fmaf(-a.y, s.y, v.x));
        float si = fmaf(a.x, s.y, fmaf(a.y, s.x, v.y));
        s.x = sr; s.y = si;
    }
    d_fin[t] = s;
}

// Pass 2: per (b,p) prefix across 16 chunks with A = Lambda_bar^256.
__global__ void __launch_bounds__(256) k_scan2() {
    int t = blockIdx.x * 256 + threadIdx.x;     // b*PD + p
    int p = t & (PD - 1);
    int b = t >> 8;
    float2 A = d_A256[p];
    float2 c = make_float2(0.0f, 0.0f);
    #pragma unroll
    for (int ch = 0; ch < NCH; ch++) {
        int idx = (b * NCH + ch) * PD + p;
        d_carry[idx] = c;
        float2 f = d_fin[idx];
        float cr = fmaf(A.x, c.x, fmaf(-A.y, c.y, f.x));
        float ci = fmaf(A.x, c.y, fmaf(A.y, c.x, f.y));
        c.x = cr; c.y = ci;
    }
}

// Pass 3: local scan again, initialized with carry; write xs.
__global__ void __launch_bounds__(256) k_scan3() {
    int t = blockIdx.x * 256 + threadIdx.x;
    int p = t & (PD - 1);
    float2 a = d_Lb[p];
    size_t base = (size_t)(t >> 8) * (CLEN * PD) + p;
    const float2* bu = (const float2*)d_Bu + base;
    float2*       xs = (float2*)d_xs + base;
    float2 s = d_carry[t];
    #pragma unroll 4
    for (int l = 0; l < CLEN; l++) {
        float2 v = bu[(size_t)l * PD];
        float sr = fmaf(a.x, s.x, fmaf(-a.y, s.y, v.x));
        float si = fmaf(a.x, s.y, fmaf(a.y, s.x, v.y));
        s.x = sr; s.y = si;
        xs[(size_t)l * PD] = s;
    }
}

// ---------------- launch ------------------------------------------------------
extern "C" void kernel_launch(void* const* d_in, const int* in_sizes, int n_in,
                              void* d_out, int out_size) {
    const float* x    = (const float*)d_in[0];
    const float* Lre  = (const float*)d_in[1];
    const float* Lim  = (const float*)d_in[2];
    const float* Bin  = (const float*)d_in[3];
    const float* Cin  = (const float*)d_in[4];
    const float* Dv   = (const float*)d_in[5];
    const float* ls   = (const float*)d_in[6];
    float* out = (float*)d_out;

    float *pW1 = nullptr, *pW2 = nullptr, *pBu = nullptr, *pxs = nullptr;
    cudaGetSymbolAddress((void**)&pW1, d_W1);
    cudaGetSymbolAddress((void**)&pW2, d_W2);
    cudaGetSymbolAddress((void**)&pBu, d_Bu);
    cudaGetSymbolAddress((void**)&pxs, d_xs);

    k_prep1<<<1, 256>>>(Lre, Lim, ls);
    k_prep2<<<(PD * HD + 255) / 256, 256>>>(Bin, Cin);

    dim3 grid(NN / 128, MM / 128);   // (4, 256)
    sgemm128<false><<<grid, 256>>>(x, pW1, pBu, nullptr, nullptr);

    k_scan1<<<(BSZ * NCH * PD) / 256, 256>>>();
    k_scan2<<<(BSZ * PD) / 256, 256>>>();
    k_scan3<<<(BSZ * NCH * PD) / 256, 256>>>();

    sgemm128<true><<<grid, 256>>>(pxs, pW2, out, x, Dv);
}

// round 3
// speedup vs baseline: 1.5904x; 1.5904x over previous
#include <cuda_runtime.h>
#include <cuda_bf16.h>
#include <cstdint>
#include <cstddef>

// ---------------- problem constants ------------------------------------------
#define BSZ  8
#define LEN  4096
#define HD   512
#define PD   256
#define MM   (BSZ * LEN)   // 32768
#define KD   512           // GEMM K (both GEMMs)
#define ND   512           // GEMM N (both GEMMs)
#define NCH  64            // scan chunks per sequence
#define CLEN 64            // chunk length (NCH*CLEN == LEN)

// ---------------- device scratch ---------------------------------------------
__device__ __align__(128) __nv_bfloat16 d_xhi[(size_t)MM * KD];     // 32 MB
__device__ __align__(128) __nv_bfloat16 d_xlo[(size_t)MM * KD];     // 32 MB
__device__ __align__(128) __nv_bfloat16 d_xshi[(size_t)MM * KD];    // 32 MB
__device__ __align__(128) __nv_bfloat16 d_xslo[(size_t)MM * KD];    // 32 MB
__device__ __align__(128) float         d_Bu[(size_t)MM * ND];      // 64 MB
__device__ __align__(128) __nv_bfloat16 d_W1t_hi[ND * KD];          // [n=2p+j][k=h]
__device__ __align__(128) __nv_bfloat16 d_W1t_lo[ND * KD];
__device__ __align__(128) __nv_bfloat16 d_W2t_hi[ND * KD];          // [n=h][k=2p+j]
__device__ __align__(128) __nv_bfloat16 d_W2t_lo[ND * KD];
__device__ float2 d_Lb[PD];
__device__ float2 d_gamma[PD];
__device__ float2 d_Ach[PD];
__device__ float2 d_fin[BSZ * NCH * PD];
__device__ float2 d_carry[BSZ * NCH * PD];

// ---------------- helpers ------------------------------------------------------
__device__ __forceinline__ uint32_t smem_u32(const void* p) {
    uint32_t a;
    asm("{ .reg .u64 t; cvta.to.shared.u64 t, %1; cvt.u32.u64 %0, t; }" : "=r"(a) : "l"(p));
    return a;
}
__device__ __forceinline__ uint32_t swz128(uint32_t o) { return o ^ ((o >> 3) & 0x70); }

__device__ __forceinline__ void cp16(uint32_t s, const void* g) {
    asm volatile("cp.async.cg.shared.global [%0], [%1], 16;" :: "r"(s), "l"(g) : "memory");
}
#define CP_COMMIT() asm volatile("cp.async.commit_group;" ::: "memory")
#define CP_WAIT2()  asm volatile("cp.async.wait_group 2;" ::: "memory")
#define CP_WAIT0()  asm volatile("cp.async.wait_group 0;" ::: "memory")

__device__ __forceinline__ void ldsm4(uint32_t* r, uint32_t addr) {
    asm volatile("ldmatrix.sync.aligned.m8n8.x4.shared.b16 {%0,%1,%2,%3}, [%4];"
                 : "=r"(r[0]), "=r"(r[1]), "=r"(r[2]), "=r"(r[3]) : "r"(addr));
}
__device__ __forceinline__ void mma_bf16(float* d, const uint32_t* a, const uint32_t* b) {
    asm volatile(
        "mma.sync.aligned.m16n8k16.row.col.f32.bf16.bf16.f32 "
        "{%0,%1,%2,%3}, {%4,%5,%6,%7}, {%8,%9}, {%0,%1,%2,%3};"
        : "+f"(d[0]), "+f"(d[1]), "+f"(d[2]), "+f"(d[3])
        : "r"(a[0]), "r"(a[1]), "r"(a[2]), "r"(a[3]), "r"(b[0]), "r"(b[1]));
}
__device__ __forceinline__ void split1(float v, __nv_bfloat16& h, __nv_bfloat16& l) {
    h = __float2bfloat16_rn(v);
    l = __float2bfloat16_rn(v - __bfloat162float(h));
}

// ---------------- prep kernels ------------------------------------------------
__global__ void k_prep1(const float* __restrict__ Lre, const float* __restrict__ Lim,
                        const float* __restrict__ lstep) {
    int p = threadIdx.x;
    if (p < PD) {
        float step = expf(lstep[p]);
        float re = Lre[p], im = Lim[p];
        float er = expf(re * step);
        float sphi, cphi;
        sincosf(im * step, &sphi, &cphi);
        float2 Lb = make_float2(er * cphi, er * sphi);
        float nr = Lb.x - 1.0f, ni = Lb.y;
        float den = re * re + im * im;
        d_Lb[p] = Lb;
        d_gamma[p] = make_float2((nr * re + ni * im) / den, (ni * re - nr * im) / den);
        float2 a = Lb;
        #pragma unroll
        for (int i = 0; i < 6; i++) {   // Lb^64
            float ar = a.x * a.x - a.y * a.y;
            float ai = 2.0f * a.x * a.y;
            a = make_float2(ar, ai);
        }
        d_Ach[p] = a;
    }
}

__global__ void k_prep2(const float* __restrict__ Bin, const float* __restrict__ Cin) {
    int idx = blockIdx.x * blockDim.x + threadIdx.x;
    if (idx < PD * HD) {
        int p = idx / HD, h = idx % HD;
        float2 g = d_gamma[p];
        float br = Bin[(p * HD + h) * 2 + 0];
        float bi = Bin[(p * HD + h) * 2 + 1];
        float w1r = g.x * br - g.y * bi;   // n = 2p
        float w1i = g.x * bi + g.y * br;   // n = 2p+1
        __nv_bfloat16 hh, ll;
        split1(w1r, hh, ll); d_W1t_hi[(2 * p + 0) * KD + h] = hh; d_W1t_lo[(2 * p + 0) * KD + h] = ll;
        split1(w1i, hh, ll); d_W1t_hi[(2 * p + 1) * KD + h] = hh; d_W1t_lo[(2 * p + 1) * KD + h] = ll;
        float cr = Cin[(h * PD + p) * 2 + 0];
        float ci = Cin[(h * PD + p) * 2 + 1];
        split1( 2.0f * cr, hh, ll); d_W2t_hi[h * KD + 2 * p + 0] = hh; d_W2t_lo[h * KD + 2 * p + 0] = ll;
        split1(-2.0f * ci, hh, ll); d_W2t_hi[h * KD + 2 * p + 1] = hh; d_W2t_lo[h * KD + 2 * p + 1] = ll;
    }
}

__global__ void __launch_bounds__(256) k_split(const float* __restrict__ x) {
    size_t i = (size_t)blockIdx.x * 256 + threadIdx.x;
    float4 v = *(const float4*)(x + i * 4);
    __nv_bfloat16 h0, h1, h2, h3, l0, l1, l2, l3;
    split1(v.x, h0, l0); split1(v.y, h1, l1); split1(v.z, h2, l2); split1(v.w, h3, l3);
    __nv_bfloat162 hi01 = __halves2bfloat162(h0, h1), hi23 = __halves2bfloat162(h2, h3);
    __nv_bfloat162 lo01 = __halves2bfloat162(l0, l1), lo23 = __halves2bfloat162(l2, l3);
    ((uint2*)d_xhi)[i] = make_uint2(*(uint32_t*)&hi01, *(uint32_t*)&hi23);
    ((uint2*)d_xlo)[i] = make_uint2(*(uint32_t*)&lo01, *(uint32_t*)&lo23);
}

// ---------------- HMMA GEMM: 128x128 CTA, 8 warps (32x64), K chunks of 64 ------
// smem: 4 stages x (A 16KB + B 16KB) = 128KB
#define NSTAGE 4
#define CHK    64
#define STG_A(s)  ((s) * 16384u)
#define STG_B(s)  (65536u + (s) * 16384u)
#define GSM_TOTAL 131072

__device__ __forceinline__ void load_chunk(uint32_t sb, int stage, int tid,
                                           const __nv_bfloat16* __restrict__ A,
                                           const __nv_bfloat16* __restrict__ W,
                                           int m0, int n0, int kc) {
    uint32_t abase = sb + STG_A(stage);
    uint32_t bbase = sb + STG_B(stage);
    #pragma unroll
    for (int i = 0; i < 4; i++) {
        int s = tid + i * 256;           // 0..1023
        int row = s >> 3, c16 = (s & 7); // 128 rows x 8 x 16B
        cp16(abase + swz128(row * 128 + c16 * 16), A + (size_t)(m0 + row) * KD + kc + c16 * 8);
    }
    #pragma unroll
    for (int i = 0; i < 4; i++) {
        int s = tid + i * 256;
        int row = s >> 3, c16 = (s & 7);
        cp16(bbase + swz128(row * 128 + c16 * 16), W + (size_t)(n0 + row) * KD + kc + c16 * 8);
    }
    CP_COMMIT();
}

template <bool EPI>
__global__ void __launch_bounds__(256, 1)
gemm_hmma(const __nv_bfloat16* __restrict__ Ahi, const __nv_bfloat16* __restrict__ Alo,
          const __nv_bfloat16* __restrict__ Whi, const __nv_bfloat16* __restrict__ Wlo,
          float* __restrict__ Cout, const float* __restrict__ Xs, const float* __restrict__ Dv) {
    extern __shared__ char smem[];
    uint32_t sb = smem_u32(smem);
    const int tid = threadIdx.x, wid = tid >> 5, lane = tid & 31;
    const int wm = wid & 3, wn = wid >> 2;            // 4 x 2 warp grid
    const int m0 = blockIdx.y * 128, n0 = blockIdx.x * 128;

    const __nv_bfloat16* APASS[3] = {Ahi, Alo, Ahi};
    const __nv_bfloat16* BPASS[3] = {Whi, Whi, Wlo};

    float acc[2][8][4];
    #pragma unroll
    for (int i = 0; i < 2; i++)
        #pragma unroll
        for (int j = 0; j < 8; j++)
            #pragma unroll
            for (int q = 0; q < 4; q++) acc[i][j][q] = 0.0f;

    // ldmatrix per-lane base coordinates
    const int rowA = wm * 32 + (lane & 15);           // + mt*16
    const int colA = (lane >> 4) * 16;                // bytes, + ks*32
    const int rowB = wn * 64 + ((lane >> 4) & 1) * 8 + (lane & 7);  // + nt2*16
    const int colB = ((lane >> 3) & 1) * 16;          // bytes, + ks*32

    const int NC = 24;                                // 3 passes x 8 chunks
    load_chunk(sb, 0, tid, APASS[0], BPASS[0], m0, n0, 0);
    load_chunk(sb, 1, tid, APASS[0], BPASS[0], m0, n0, 64);
    load_chunk(sb, 2, tid, APASS[0], BPASS[0], m0, n0, 128);

    for (int c = 0; c < NC; c++) {
        CP_WAIT2();
        __syncthreads();
        // prefetch chunk c+3 into stage (c+3)&3 (that stage finished compute last iter)
        if (c + 3 < NC) {
            int cn = c + 3;
            load_chunk(sb, cn & 3, tid, APASS[cn >> 3], BPASS[cn >> 3], m0, n0, (cn & 7) * CHK);
        } else {
            CP_COMMIT();   // keep group accounting uniform
        }
        // compute stage c&3
        uint32_t aB = sb + STG_A(c & 3);
        uint32_t bB = sb + STG_B(c & 3);
        #pragma unroll
        for (int ks = 0; ks < 4; ks++) {
            uint32_t afr[2][4], bfr[4][4];
            #pragma unroll
            for (int mt = 0; mt < 2; mt++)
                ldsm4(afr[mt], aB + swz128((rowA + mt * 16) * 128 + ks * 32 + colA));
            #pragma unroll
            for (int nt2 = 0; nt2 < 4; nt2++)
                ldsm4(bfr[nt2], bB + swz128((rowB + nt2 * 16) * 128 + ks * 32 + colB));
            #pragma unroll
            for (int mt = 0; mt < 2; mt++)
                #pragma unroll
                for (int nt = 0; nt < 8; nt++)
                    mma_bf16(acc[mt][nt], afr[mt], &bfr[nt >> 1][(nt & 1) * 2]);
        }
    }
    CP_WAIT0();

    // epilogue: d0,d1 -> (row g, col 2t..2t+1); d2,d3 -> row g+8
    const int g = lane >> 2, tig = lane & 3;
    #pragma unroll
    for (int mt = 0; mt < 2; mt++) {
        #pragma unroll
        for (int nt = 0; nt < 8; nt++) {
            int r0 = m0 + wm * 32 + mt * 16 + g;
            int cc = n0 + wn * 64 + nt * 8 + tig * 2;
            float2 v0 = make_float2(acc[mt][nt][0], acc[mt][nt][1]);
            float2 v1 = make_float2(acc[mt][nt][2], acc[mt][nt][3]);
            if (EPI) {
                float2 dv = *(const float2*)(Dv + cc);
                float2 x0 = *(const float2*)(Xs + (size_t)r0 * ND + cc);
                float2 x1 = *(const float2*)(Xs + (size_t)(r0 + 8) * ND + cc);
                v0.x = fmaf(dv.x, x0.x, v0.x); v0.y = fmaf(dv.y, x0.y, v0.y);
                v1.x = fmaf(dv.x, x1.x, v1.x); v1.y = fmaf(dv.y, x1.y, v1.y);
            }
            *(float2*)(Cout + (size_t)r0 * ND + cc) = v0;
            *(float2*)(Cout + (size_t)(r0 + 8) * ND + cc) = v1;
        }
    }
}

// ---------------- chunked complex scan ----------------------------------------
__global__ void __launch_bounds__(256) k_scan1() {
    int t = blockIdx.x * 256 + threadIdx.x;          // (b*NCH+ch)*PD + p
    int p = t & (PD - 1);
    float2 a = d_Lb[p];
    const float2* bu = (const float2*)d_Bu + (size_t)(t >> 8) * (CLEN * PD) + p;
    float2 s = make_float2(0.0f, 0.0f);
    #pragma unroll 4
    for (int l = 0; l < CLEN; l++) {
        float2 v = bu[(size_t)l * PD];
        float sr = fmaf(a.x, s.x, fmaf(-a.y, s.y, v.x));
        float si = fmaf(a.x, s.y, fmaf(a.y, s.x, v.y));
        s.x = sr; s.y = si;
    }
    d_fin[t] = s;
}

__global__ void __launch_bounds__(256) k_scan2() {
    int t = blockIdx.x * 256 + threadIdx.x;          // b*PD + p
    int p = t & (PD - 1);
    int b = t >> 8;
    float2 A = d_Ach[p];
    float2 c = make_float2(0.0f, 0.0f);
    for (int ch = 0; ch < NCH; ch++) {
        int idx = (b * NCH + ch) * PD + p;
        d_carry[idx] = c;
        float2 f = d_fin[idx];
        float cr = fmaf(A.x, c.x, fmaf(-A.y, c.y, f.x));
        float ci = fmaf(A.x, c.y, fmaf(A.y, c.x, f.y));
        c.x = cr; c.y = ci;
    }
}

__global__ void __launch_bounds__(256) k_scan3() {
    int t = blockIdx.x * 256 + threadIdx.x;
    int p = t & (PD - 1);
    float2 a = d_Lb[p];
    size_t mbase = (size_t)(t >> 8) * CLEN;
    const float2* bu = (const float2*)d_Bu + mbase * PD + p;
    float2 s = d_carry[t];
    #pragma unroll 4
    for (int l = 0; l < CLEN; l++) {
        float2 v = bu[(size_t)l * PD];
        float sr = fmaf(a.x, s.x, fmaf(-a.y, s.y, v.x));
        float si = fmaf(a.x, s.y, fmaf(a.y, s.x, v.y));
        s.x = sr; s.y = si;
        __nv_bfloat16 hr, lr, hi, li;
        split1(sr, hr, lr);
        split1(si, hi, li);
        size_t off = (mbase + l) * ND + 2 * p;
        __nv_bfloat162 hv = __halves2bfloat162(hr, hi);
        __nv_bfloat162 lv = __halves2bfloat162(lr, li);
        *(uint32_t*)(d_xshi + off) = *(uint32_t*)&hv;
        *(uint32_t*)(d_xslo + off) = *(uint32_t*)&lv;
    }
}

// ---------------- launch -------------------------------------------------------
extern "C" void kernel_launch(void* const* d_in, const int* in_sizes, int n_in,
                              void* d_out, int out_size) {
    const float* x   = (const float*)d_in[0];
    const float* Lre = (const float*)d_in[1];
    const float* Lim = (const float*)d_in[2];
    const float* Bin = (const float*)d_in[3];
    const float* Cin = (const float*)d_in[4];
    const float* Dv  = (const float*)d_in[5];
    const float* ls  = (const float*)d_in[6];
    float* out = (float*)d_out;

    __nv_bfloat16 *pxhi, *pxlo, *pxshi, *pxslo, *pW1h, *pW1l, *pW2h, *pW2l;
    float* pBu;
    cudaGetSymbolAddress((void**)&pxhi,  d_xhi);
    cudaGetSymbolAddress((void**)&pxlo,  d_xlo);
    cudaGetSymbolAddress((void**)&pxshi, d_xshi);
    cudaGetSymbolAddress((void**)&pxslo, d_xslo);
    cudaGetSymbolAddress((void**)&pW1h,  d_W1t_hi);
    cudaGetSymbolAddress((void**)&pW1l,  d_W1t_lo);
    cudaGetSymbolAddress((void**)&pW2h,  d_W2t_hi);
    cudaGetSymbolAddress((void**)&pW2l,  d_W2t_lo);
    cudaGetSymbolAddress((void**)&pBu,   d_Bu);

    cudaFuncSetAttribute(gemm_hmma<false>, cudaFuncAttributeMaxDynamicSharedMemorySize, GSM_TOTAL);
    cudaFuncSetAttribute(gemm_hmma<true>,  cudaFuncAttributeMaxDynamicSharedMemorySize, GSM_TOTAL);

    k_prep1<<<1, 256>>>(Lre, Lim, ls);
    k_prep2<<<(PD * HD + 255) / 256, 256>>>(Bin, Cin);
    k_split<<<(int)(((size_t)MM * KD / 4) / 256), 256>>>(x);

    dim3 ggrid(ND / 128, MM / 128);   // (4, 256)
    gemm_hmma<false><<<ggrid, 256, GSM_TOTAL>>>(pxhi, pxlo, pW1h, pW1l, pBu, nullptr, nullptr);

    k_scan1<<<(BSZ * NCH * PD) / 256, 256>>>();
    k_scan2<<<(BSZ * PD) / 256, 256>>>();
    k_scan3<<<(BSZ * NCH * PD) / 256, 256>>>();

    gemm_hmma<true><<<ggrid, 256, GSM_TOTAL>>>(pxshi, pxslo, pW2h, pW2l, out, x, Dv);
}

// round 4
// speedup vs baseline: 2.6689x; 1.6781x over previous
#include <cuda_runtime.h>
#include <cuda_bf16.h>
#include <cstdint>
#include <cstddef>

// ---------------- problem constants ------------------------------------------
#define BSZ  8
#define LEN  4096
#define HD   512
#define PD   256
#define MM   (BSZ * LEN)   // 32768
#define KD   512           // GEMM K (both GEMMs)
#define ND   512           // GEMM N (both GEMMs)
#define NCH  64            // scan chunks per sequence
#define CLEN 64            // chunk length (NCH*CLEN == LEN)

// ---------------- device scratch ---------------------------------------------
__device__ __align__(128) __nv_bfloat16 d_xhi[(size_t)MM * KD];     // 32 MB
__device__ __align__(128) __nv_bfloat16 d_xlo[(size_t)MM * KD];     // 32 MB
__device__ __align__(128) __nv_bfloat16 d_xshi[(size_t)MM * KD];    // 32 MB
__device__ __align__(128) __nv_bfloat16 d_xslo[(size_t)MM * KD];    // 32 MB
__device__ __align__(128) float         d_Bu[(size_t)MM * ND];      // 64 MB
__device__ __align__(128) __nv_bfloat16 d_W1t_hi[ND * KD];          // [n=2p+j][k=h]
__device__ __align__(128) __nv_bfloat16 d_W1t_lo[ND * KD];
__device__ __align__(128) __nv_bfloat16 d_W2t_hi[ND * KD];          // [n=h][k=2p+j]
__device__ __align__(128) __nv_bfloat16 d_W2t_lo[ND * KD];
__device__ float2 d_Lb[PD];
__device__ float2 d_gamma[PD];
__device__ float2 d_Ach[PD];
__device__ float2 d_fin[BSZ * NCH * PD];
__device__ float2 d_carry[BSZ * NCH * PD];

// ---------------- helpers ------------------------------------------------------
__device__ __forceinline__ uint32_t smem_u32(const void* p) {
    uint32_t a;
    asm("{ .reg .u64 t; cvta.to.shared.u64 t, %1; cvt.u32.u64 %0, t; }" : "=r"(a) : "l"(p));
    return a;
}
__device__ __forceinline__ uint32_t swz128(uint32_t o) { return o ^ ((o >> 3) & 0x70); }

__device__ __forceinline__ void cp16(uint32_t s, const void* g) {
    asm volatile("cp.async.cg.shared.global [%0], [%1], 16;" :: "r"(s), "l"(g) : "memory");
}
#define CP_COMMIT() asm volatile("cp.async.commit_group;" ::: "memory")
#define CP_WAIT1()  asm volatile("cp.async.wait_group 1;" ::: "memory")
#define CP_WAIT0()  asm volatile("cp.async.wait_group 0;" ::: "memory")

__device__ __forceinline__ void ldsm4(uint32_t* r, uint32_t addr) {
    asm volatile("ldmatrix.sync.aligned.m8n8.x4.shared.b16 {%0,%1,%2,%3}, [%4];"
                 : "=r"(r[0]), "=r"(r[1]), "=r"(r[2]), "=r"(r[3]) : "r"(addr));
}
__device__ __forceinline__ void mma_bf16(float* d, const uint32_t* a, const uint32_t* b) {
    asm volatile(
        "mma.sync.aligned.m16n8k16.row.col.f32.bf16.bf16.f32 "
        "{%0,%1,%2,%3}, {%4,%5,%6,%7}, {%8,%9}, {%0,%1,%2,%3};"
        : "+f"(d[0]), "+f"(d[1]), "+f"(d[2]), "+f"(d[3])
        : "r"(a[0]), "r"(a[1]), "r"(a[2]), "r"(a[3]), "r"(b[0]), "r"(b[1]));
}
__device__ __forceinline__ void split1(float v, __nv_bfloat16& h, __nv_bfloat16& l) {
    h = __float2bfloat16_rn(v);
    l = __float2bfloat16_rn(v - __bfloat162float(h));
}

// ---------------- prep kernels ------------------------------------------------
__global__ void k_prep1(const float* __restrict__ Lre, const float* __restrict__ Lim,
                        const float* __restrict__ lstep) {
    int p = threadIdx.x;
    if (p < PD) {
        float step = expf(lstep[p]);
        float re = Lre[p], im = Lim[p];
        float er = expf(re * step);
        float sphi, cphi;
        sincosf(im * step, &sphi, &cphi);
        float2 Lb = make_float2(er * cphi, er * sphi);
        float nr = Lb.x - 1.0f, ni = Lb.y;
        float den = re * re + im * im;
        d_Lb[p] = Lb;
        d_gamma[p] = make_float2((nr * re + ni * im) / den, (ni * re - nr * im) / den);
        float2 a = Lb;
        #pragma unroll
        for (int i = 0; i < 6; i++) {   // Lb^64
            float ar = a.x * a.x - a.y * a.y;
            float ai = 2.0f * a.x * a.y;
            a = make_float2(ar, ai);
        }
        d_Ach[p] = a;
    }
}

__global__ void k_prep2(const float* __restrict__ Bin, const float* __restrict__ Cin) {
    int idx = blockIdx.x * blockDim.x + threadIdx.x;
    if (idx < PD * HD) {
        int p = idx / HD, h = idx % HD;
        float2 g = d_gamma[p];
        float br = Bin[(p * HD + h) * 2 + 0];
        float bi = Bin[(p * HD + h) * 2 + 1];
        float w1r = g.x * br - g.y * bi;   // n = 2p
        float w1i = g.x * bi + g.y * br;   // n = 2p+1
        __nv_bfloat16 hh, ll;
        split1(w1r, hh, ll); d_W1t_hi[(2 * p + 0) * KD + h] = hh; d_W1t_lo[(2 * p + 0) * KD + h] = ll;
        split1(w1i, hh, ll); d_W1t_hi[(2 * p + 1) * KD + h] = hh; d_W1t_lo[(2 * p + 1) * KD + h] = ll;
        float cr = Cin[(h * PD + p) * 2 + 0];
        float ci = Cin[(h * PD + p) * 2 + 1];
        split1( 2.0f * cr, hh, ll); d_W2t_hi[h * KD + 2 * p + 0] = hh; d_W2t_lo[h * KD + 2 * p + 0] = ll;
        split1(-2.0f * ci, hh, ll); d_W2t_hi[h * KD + 2 * p + 1] = hh; d_W2t_lo[h * KD + 2 * p + 1] = ll;
    }
}

__global__ void __launch_bounds__(256) k_split(const float* __restrict__ x) {
    size_t i = (size_t)blockIdx.x * 256 + threadIdx.x;
    float4 v = *(const float4*)(x + i * 4);
    __nv_bfloat16 h0, h1, h2, h3, l0, l1, l2, l3;
    split1(v.x, h0, l0); split1(v.y, h1, l1); split1(v.z, h2, l2); split1(v.w, h3, l3);
    __nv_bfloat162 hi01 = __halves2bfloat162(h0, h1), hi23 = __halves2bfloat162(h2, h3);
    __nv_bfloat162 lo01 = __halves2bfloat162(l0, l1), lo23 = __halves2bfloat162(l2, l3);
    ((uint2*)d_xhi)[i] = make_uint2(*(uint32_t*)&hi01, *(uint32_t*)&hi23);
    ((uint2*)d_xlo)[i] = make_uint2(*(uint32_t*)&lo01, *(uint32_t*)&lo23);
}

// ---------------- HMMA GEMM: 128x128 CTA, 8 warps (32x64), K chunks of 64 ------
// smem: 3 stages x (A 16KB + B 16KB) = 96KB  -> 2 CTAs/SM
#define NSTAGE 3
#define CHK    64
#define STG_A(s)  ((s) * 16384u)
#define STG_B(s)  (49152u + (s) * 16384u)
#define GSM_TOTAL 98304

__device__ __forceinline__ void load_chunk(uint32_t sb, int stage, int tid,
                                           const __nv_bfloat16* __restrict__ A,
                                           const __nv_bfloat16* __restrict__ W,
                                           int m0, int n0, int kc) {
    uint32_t abase = sb + STG_A(stage);
    uint32_t bbase = sb + STG_B(stage);
    #pragma unroll
    for (int i = 0; i < 4; i++) {
        int s = tid + i * 256;           // 0..1023
        int row = s >> 3, c16 = (s & 7); // 128 rows x 8 x 16B
        cp16(abase + swz128(row * 128 + c16 * 16), A + (size_t)(m0 + row) * KD + kc + c16 * 8);
    }
    #pragma unroll
    for (int i = 0; i < 4; i++) {
        int s = tid + i * 256;
        int row = s >> 3, c16 = (s & 7);
        cp16(bbase + swz128(row * 128 + c16 * 16), W + (size_t)(n0 + row) * KD + kc + c16 * 8);
    }
    CP_COMMIT();
}

template <bool EPI>
__global__ void __launch_bounds__(256, 2)
gemm_hmma(const __nv_bfloat16* __restrict__ Ahi, const __nv_bfloat16* __restrict__ Alo,
          const __nv_bfloat16* __restrict__ Whi, const __nv_bfloat16* __restrict__ Wlo,
          float* __restrict__ Cout, const float* __restrict__ Xs, const float* __restrict__ Dv) {
    extern __shared__ char smem[];
    uint32_t sb = smem_u32(smem);
    const int tid = threadIdx.x, wid = tid >> 5, lane = tid & 31;
    const int wm = wid & 3, wn = wid >> 2;            // 4 x 2 warp grid
    const int m0 = blockIdx.y * 128, n0 = blockIdx.x * 128;

    const __nv_bfloat16* APASS[3] = {Ahi, Alo, Ahi};
    const __nv_bfloat16* BPASS[3] = {Whi, Whi, Wlo};

    float acc[2][8][4];
    #pragma unroll
    for (int i = 0; i < 2; i++)
        #pragma unroll
        for (int j = 0; j < 8; j++)
            #pragma unroll
            for (int q = 0; q < 4; q++) acc[i][j][q] = 0.0f;

    // ldmatrix per-lane base byte offsets (within a stage)
    const uint32_t offA0 = swz128((wm * 32 + (lane & 15)) * 128 + (lane >> 4) * 16);
    const uint32_t offA1 = swz128((wm * 32 + 16 + (lane & 15)) * 128 + (lane >> 4) * 16);
    const int rowB = wn * 64 + ((lane >> 4) & 1) * 8 + (lane & 7);
    const uint32_t offB = ((lane >> 3) & 1) * 16;

    const int NC = 24;                                // 3 passes x 8 chunks
    load_chunk(sb, 0, tid, APASS[0], BPASS[0], m0, n0, 0);
    load_chunk(sb, 1, tid, APASS[0], BPASS[0], m0, n0, 64);

    for (int c = 0; c < NC; c++) {
        CP_WAIT1();
        __syncthreads();
        // prefetch chunk c+2 into stage (c+2)%3 (computed at iter c-1; safe after sync)
        if (c + 2 < NC) {
            int cn = c + 2;
            load_chunk(sb, cn % 3, tid, APASS[cn >> 3], BPASS[cn >> 3], m0, n0, (cn & 7) * CHK);
        } else {
            CP_COMMIT();   // keep group accounting uniform
        }
        // compute stage c%3
        uint32_t aB = sb + STG_A(c % 3);
        uint32_t bB = sb + STG_B(c % 3);
        #pragma unroll
        for (int ks = 0; ks < 4; ks++) {
            uint32_t afr[2][4], bfr[4][4];
            ldsm4(afr[0], aB + (swz128(ks * 32) ^ offA0));
            ldsm4(afr[1], aB + (swz128(ks * 32) ^ offA1));
            #pragma unroll
            for (int nt2 = 0; nt2 < 4; nt2++)
                ldsm4(bfr[nt2], bB + swz128((rowB + nt2 * 16) * 128 + ks * 32 + offB));
            #pragma unroll
            for (int mt = 0; mt < 2; mt++)
                #pragma unroll
                for (int nt = 0; nt < 8; nt++)
                    mma_bf16(acc[mt][nt], afr[mt], &bfr[nt >> 1][(nt & 1) * 2]);
        }
    }
    CP_WAIT0();

    // epilogue: d0,d1 -> (row g, col 2t..2t+1); d2,d3 -> row g+8
    const int g = lane >> 2, tig = lane & 3;
    #pragma unroll
    for (int mt = 0; mt < 2; mt++) {
        #pragma unroll
        for (int nt = 0; nt < 8; nt++) {
            int r0 = m0 + wm * 32 + mt * 16 + g;
            int cc = n0 + wn * 64 + nt * 8 + tig * 2;
            float2 v0 = make_float2(acc[mt][nt][0], acc[mt][nt][1]);
            float2 v1 = make_float2(acc[mt][nt][2], acc[mt][nt][3]);
            if (EPI) {
                float2 dv = *(const float2*)(Dv + cc);
                float2 x0 = *(const float2*)(Xs + (size_t)r0 * ND + cc);
                float2 x1 = *(const float2*)(Xs + (size_t)(r0 + 8) * ND + cc);
                v0.x = fmaf(dv.x, x0.x, v0.x); v0.y = fmaf(dv.y, x0.y, v0.y);
                v1.x = fmaf(dv.x, x1.x, v1.x); v1.y = fmaf(dv.y, x1.y, v1.y);
            }
            *(float2*)(Cout + (size_t)r0 * ND + cc) = v0;
            *(float2*)(Cout + (size_t)(r0 + 8) * ND + cc) = v1;
        }
    }
}

// ---------------- chunked complex scan ----------------------------------------
__global__ void __launch_bounds__(256) k_scan1() {
    int t = blockIdx.x * 256 + threadIdx.x;          // (b*NCH+ch)*PD + p
    int p = t & (PD - 1);
    float2 a = d_Lb[p];
    const float2* bu = (const float2*)d_Bu + (size_t)(t >> 8) * (CLEN * PD) + p;
    float2 s = make_float2(0.0f, 0.0f);
    #pragma unroll 4
    for (int l = 0; l < CLEN; l++) {
        float2 v = bu[(size_t)l * PD];
        float sr = fmaf(a.x, s.x, fmaf(-a.y, s.y, v.x));
        float si = fmaf(a.x, s.y, fmaf(a.y, s.x, v.y));
        s.x = sr; s.y = si;
    }
    d_fin[t] = s;
}

__global__ void __launch_bounds__(256) k_scan2() {
    int t = blockIdx.x * 256 + threadIdx.x;          // b*PD + p
    int p = t & (PD - 1);
    int b = t >> 8;
    float2 A = d_Ach[p];
    float2 c = make_float2(0.0f, 0.0f);
    for (int ch = 0; ch < NCH; ch++) {
        int idx = (b * NCH + ch) * PD + p;
        d_carry[idx] = c;
        float2 f = d_fin[idx];
        float cr = fmaf(A.x, c.x, fmaf(-A.y, c.y, f.x));
        float ci = fmaf(A.x, c.y, fmaf(A.y, c.x, f.y));
        c.x = cr; c.y = ci;
    }
}

__global__ void __launch_bounds__(256) k_scan3() {
    int t = blockIdx.x * 256 + threadIdx.x;
    int p = t & (PD - 1);
    float2 a = d_Lb[p];
    size_t mbase = (size_t)(t >> 8) * CLEN;
    const float2* bu = (const float2*)d_Bu + mbase * PD + p;
    float2 s = d_carry[t];
    #pragma unroll 4
    for (int l = 0; l < CLEN; l++) {
        float2 v = bu[(size_t)l * PD];
        float sr = fmaf(a.x, s.x, fmaf(-a.y, s.y, v.x));
        float si = fmaf(a.x, s.y, fmaf(a.y, s.x, v.y));
        s.x = sr; s.y = si;
        __nv_bfloat16 hr, lr, hi, li;
        split1(sr, hr, lr);
        split1(si, hi, li);
        size_t off = (mbase + l) * ND + 2 * p;
        __nv_bfloat162 hv = __halves2bfloat162(hr, hi);
        __nv_bfloat162 lv = __halves2bfloat162(lr, li);
        *(uint32_t*)(d_xshi + off) = *(uint32_t*)&hv;
        *(uint32_t*)(d_xslo + off) = *(uint32_t*)&lv;
    }
}

// ---------------- launch -------------------------------------------------------
extern "C" void kernel_launch(void* const* d_in, const int* in_sizes, int n_in,
                              void* d_out, int out_size) {
    const float* x   = (const float*)d_in[0];
    const float* Lre = (const float*)d_in[1];
    const float* Lim = (const float*)d_in[2];
    const float* Bin = (const float*)d_in[3];
    const float* Cin = (const float*)d_in[4];
    const float* Dv  = (const float*)d_in[5];
    const float* ls  = (const float*)d_in[6];
    float* out = (float*)d_out;

    __nv_bfloat16 *pxhi, *pxlo, *pxshi, *pxslo, *pW1h, *pW1l, *pW2h, *pW2l;
    float* pBu;
    cudaGetSymbolAddress((void**)&pxhi,  d_xhi);
    cudaGetSymbolAddress((void**)&pxlo,  d_xlo);
    cudaGetSymbolAddress((void**)&pxshi, d_xshi);
    cudaGetSymbolAddress((void**)&pxslo, d_xslo);
    cudaGetSymbolAddress((void**)&pW1h,  d_W1t_hi);
    cudaGetSymbolAddress((void**)&pW1l,  d_W1t_lo);
    cudaGetSymbolAddress((void**)&pW2h,  d_W2t_hi);
    cudaGetSymbolAddress((void**)&pW2l,  d_W2t_lo);
    cudaGetSymbolAddress((void**)&pBu,   d_Bu);

    cudaFuncSetAttribute(gemm_hmma<false>, cudaFuncAttributeMaxDynamicSharedMemorySize, GSM_TOTAL);
    cudaFuncSetAttribute(gemm_hmma<true>,  cudaFuncAttributeMaxDynamicSharedMemorySize, GSM_TOTAL);

    k_prep1<<<1, 256>>>(Lre, Lim, ls);
    k_prep2<<<(PD * HD + 255) / 256, 256>>>(Bin, Cin);
    k_split<<<(int)(((size_t)MM * KD / 4) / 256), 256>>>(x);

    dim3 ggrid(ND / 128, MM / 128);   // (4, 256)
    gemm_hmma<false><<<ggrid, 256, GSM_TOTAL>>>(pxhi, pxlo, pW1h, pW1l, pBu, nullptr, nullptr);

    k_scan1<<<(BSZ * NCH * PD) / 256, 256>>>();
    k_scan2<<<(BSZ * PD) / 256, 256>>>();
    k_scan3<<<(BSZ * NCH * PD) / 256, 256>>>();

    gemm_hmma<true><<<ggrid, 256, GSM_TOTAL>>>(pxshi, pxslo, pW2h, pW2l, out, x, Dv);
}